// round 6
// baseline (speedup 1.0000x reference)
#include <cuda_runtime.h>

#define DDIM 64
#define KCODES 1024
#define BM 64
#define BK 128
#define TM 4
#define NTHREADS 256
#define HW 4096
#define NTOT (32*64*64)   /* 131072 rows */

typedef unsigned long long u64t;

__device__ __align__(16) float g_ek2[KCODES];
__device__ double g_loss;

__device__ __forceinline__ u64t pack2(float x, float y) {
    u64t r;
    asm("mov.b64 %0, {%1, %2};" : "=l"(r) : "f"(x), "f"(y));
    return r;
}
__device__ __forceinline__ void unpack2(float& x, float& y, u64t v) {
    asm("mov.b64 {%0, %1}, %2;" : "=f"(x), "=f"(y) : "l"(v));
}
__device__ __forceinline__ void ffma2(u64t& d, u64t a, u64t b) {
    asm("fma.rn.f32x2 %0, %1, %2, %3;" : "=l"(d) : "l"(a), "l"(b), "l"(d));
}
__device__ __forceinline__ u64t ffma2r(u64t a, u64t b, u64t c) {
    u64t d;
    asm("fma.rn.f32x2 %0, %1, %2, %3;" : "=l"(d) : "l"(a), "l"(b), "l"(c));
    return d;
}

__global__ void zero_loss_kernel() { g_loss = 0.0; }

__global__ void ek2_kernel(const float* __restrict__ emb) {
    int k = blockIdx.x * blockDim.x + threadIdx.x;
    if (k >= KCODES) return;
    const float4* e4 = (const float4*)(emb + (size_t)k * DDIM);
    float s = 0.f;
#pragma unroll
    for (int i = 0; i < DDIM / 4; i++) {
        float4 v = e4[i];
        s += v.x * v.x + v.y * v.y + v.z * v.z + v.w * v.w;
    }
    g_ek2[k] = s;
}

__global__ __launch_bounds__(NTHREADS)
void vq_kernel(const float* __restrict__ z, const float* __restrict__ emb,
               float* __restrict__ out) {
    __shared__ __align__(16) float zs[DDIM][BM];   // z tile, [d][i]       16 KB
    __shared__ __align__(16) float es[DDIM][BK];   // emb chunk, [d][k]    32 KB
    __shared__ float rv[BM][16];                   // per-row min vals      4 KB
    __shared__ int   ri[BM][16];                   // per-row min idx       4 KB
    __shared__ int   idx_s[BM];
    __shared__ float wsum[8];

    const int tid = threadIdx.x;
    const int tx = tid & 15;    // code dim: two dense groups of 4 -> 8 codes/thread
    const int ty = tid >> 4;    // row  dim: 16 lanes x TM=4 -> 64 rows

    const int nbase = blockIdx.x * BM;
    const int b   = nbase >> 12;       // / 4096
    const int hw0 = nbase & (HW - 1);

    // ---- load z tile: z[b, d, hw0 + i] -> zs[d][i] (coalesced, no transpose) ----
    const float* zb = z + (size_t)b * DDIM * HW + hw0;
#pragma unroll
    for (int it = 0; it < 4; it++) {
        int i4 = it * NTHREADS + tid;          // 1024 float4 total
        int d  = i4 >> 4;
        int c4 = i4 & 15;
        float4 v = *(const float4*)(zb + (size_t)d * HW + c4 * 4);
        *(float4*)(&zs[d][c4 * 4]) = v;
    }

    const u64t neg2 = pack2(-2.f, -2.f);

    float mv[TM];
    int   mi[TM];
#pragma unroll
    for (int r = 0; r < TM; r++) { mv[r] = 3.4e38f; mi[r] = 0; }

    for (int kc = 0; kc < KCODES / BK; kc++) {
        const int k0 = kc * BK;
        __syncthreads();   // protect es reuse (also covers zs on first iter)

        // ---- load emb chunk with transpose: emb[k0+k][d] -> es[d][k] ----
        {
            int k     = tid >> 1;
            int dbase = (tid & 1) * 32;
            const float4* er = (const float4*)(emb + (size_t)(k0 + k) * DDIM + dbase);
#pragma unroll
            for (int i = 0; i < 8; i++) {
                float4 v = er[i];
                int d = dbase + i * 4;
                es[d + 0][k] = v.x;
                es[d + 1][k] = v.y;
                es[d + 2][k] = v.z;
                es[d + 3][k] = v.w;
            }
        }
        __syncthreads();

        // acc2[r][j]: packed f32x2 pairs; j=0,1 -> cols 4tx+{0,1},{2,3}
        //                                  j=2,3 -> cols 64+4tx+{0,1},{2,3}
        u64t acc2[TM][4];
#pragma unroll
        for (int r = 0; r < TM; r++)
#pragma unroll
            for (int j = 0; j < 4; j++) acc2[r][j] = 0ull;

#pragma unroll 8
        for (int d = 0; d < DDIM; d++) {
            float4 a = *(const float4*)(&zs[d][ty * 4]);            // warp-broadcast
            ulonglong2 b0 = *(const ulonglong2*)(&es[d][4 * tx]);       // dense, conflict-free
            ulonglong2 b1 = *(const ulonglong2*)(&es[d][64 + 4 * tx]);
            u64t av[TM] = {pack2(a.x, a.x), pack2(a.y, a.y),
                           pack2(a.z, a.z), pack2(a.w, a.w)};
#pragma unroll
            for (int r = 0; r < TM; r++) {
                ffma2(acc2[r][0], av[r], b0.x);
                ffma2(acc2[r][1], av[r], b0.y);
                ffma2(acc2[r][2], av[r], b1.x);
                ffma2(acc2[r][3], av[r], b1.y);
            }
        }

        // ---- running min update: s = ||e||^2 - 2*dot (packed) ----
        ulonglong2 q0 = *(const ulonglong2*)(&g_ek2[k0 + 4 * tx]);
        ulonglong2 q1 = *(const ulonglong2*)(&g_ek2[k0 + 64 + 4 * tx]);
        u64t qs[4] = {q0.x, q0.y, q1.x, q1.y};
#pragma unroll
        for (int r = 0; r < TM; r++) {
#pragma unroll
            for (int j = 0; j < 4; j++) {
                u64t s2 = ffma2r(acc2[r][j], neg2, qs[j]);
                float s0, s1;
                unpack2(s0, s1, s2);
                int kb = (j < 2) ? (k0 + 4 * tx + 2 * j)
                                 : (k0 + 64 + 4 * tx + 2 * (j - 2));
                if (s0 < mv[r]) { mv[r] = s0; mi[r] = kb; }
                if (s1 < mv[r]) { mv[r] = s1; mi[r] = kb + 1; }
            }
        }
    }

    // ---- cross-thread argmin reduction (first-occurrence tie rule) ----
    __syncthreads();
#pragma unroll
    for (int r = 0; r < TM; r++) {
        rv[ty * 4 + r][tx] = mv[r];
        ri[ty * 4 + r][tx] = mi[r];
    }
    __syncthreads();
    if (tid < BM) {
        float best = rv[tid][0];
        int   bi   = ri[tid][0];
#pragma unroll
        for (int j = 1; j < 16; j++) {
            float v  = rv[tid][j];
            int   ii = ri[tid][j];
            if (v < best || (v == best && ii < bi)) { best = v; bi = ii; }
        }
        idx_s[tid] = bi;
    }
    __syncthreads();

    // ---- epilogue: gather codebook rows, transposed coalesced store, loss ----
    float* outb = out + (size_t)b * DDIM * HW + hw0;
    float lsum = 0.f;
#pragma unroll
    for (int it = 0; it < 16; it++) {
        int e = it * NTHREADS + tid;   // 4096 elements
        int d = e >> 6;
        int i = e & 63;
        float q = __ldg(&emb[(size_t)idx_s[i] * DDIM + d]);
        outb[(size_t)d * HW + i] = q;
        float diff = q - zs[d][i];
        lsum += diff * diff;
    }
    // block reduce loss
#pragma unroll
    for (int o = 16; o > 0; o >>= 1)
        lsum += __shfl_xor_sync(0xffffffffu, lsum, o);
    if ((tid & 31) == 0) wsum[tid >> 5] = lsum;
    __syncthreads();
    if (tid == 0) {
        float t = 0.f;
#pragma unroll
        for (int j = 0; j < 8; j++) t += wsum[j];
        atomicAdd(&g_loss, (double)t);
    }
}

__global__ void finalize_kernel(float* out, int loss_idx) {
    out[loss_idx] = (float)(g_loss * (1.25 / 8388608.0));
}

extern "C" void kernel_launch(void* const* d_in, const int* in_sizes, int n_in,
                              void* d_out, int out_size) {
    const float* z   = (const float*)d_in[0];
    const float* emb = (const float*)d_in[1];
    float* out = (float*)d_out;

    zero_loss_kernel<<<1, 1>>>();
    ek2_kernel<<<KCODES / 128, 128>>>(emb);
    vq_kernel<<<NTOT / BM, NTHREADS>>>(z, emb, out);
    finalize_kernel<<<1, 1>>>(out, out_size - 1);
}

// round 12
// speedup vs baseline: 1.6820x; 1.6820x over previous
#include <cuda_runtime.h>
#include <cstdint>

#define DDIM     64
#define MROWS    128
#define BK       64
#define KCODES   1024
#define NCHUNKS  (KCODES / BK)      /* 16 */
#define HW       4096
#define NTOT     (32 * 64 * 64)     /* 131072 rows */
#define NTHREADS 256
#define EPS      1e-2f              /* rescue margin; approx error bound ~1e-4 */

/* ---- dynamic smem layout (bytes) ---- */
#define SM_EK2   0                  /* 4 KB  */
#define SM_IDX   4096               /* 512 B */
#define SM_WS    4608               /* 32 B  */
#define SM_ZS    8192               /* 32 KB  zs[d][128] */
#define SM_A4    40960              /* 64 KB  A fragments */
#define SM_B4    106496             /* 32 KB  B fragments */
#define SMEM_TOTAL 139264

__device__ __align__(16) float g_ek2[KCODES];
__device__ double g_loss;

/* ================= helpers ================= */
__device__ __forceinline__ void mma_tf32(float& c0, float& c1, float& c2, float& c3,
                                         uint32_t a0, uint32_t a1, uint32_t a2, uint32_t a3,
                                         uint32_t b0, uint32_t b1) {
    asm volatile(
        "mma.sync.aligned.m16n8k8.row.col.f32.tf32.tf32.f32 "
        "{%0,%1,%2,%3},{%4,%5,%6,%7},{%8,%9},{%0,%1,%2,%3};"
        : "+f"(c0), "+f"(c1), "+f"(c2), "+f"(c3)
        : "r"(a0), "r"(a1), "r"(a2), "r"(a3), "r"(b0), "r"(b1));
}

/* split fp32 into two valid tf32 values (hi + lo ~ v, both 13 low bits zero) */
__device__ __forceinline__ void split_tf32(float v, uint32_t& hi, uint32_t& lo) {
    uint32_t h = __float_as_uint(v) & 0xFFFFE000u;
    float l = v - __uint_as_float(h);
    hi = h;
    lo = __float_as_uint(l) & 0xFFFFE000u;
}

/* exact fp32 distance, accumulation order identical to the passing scalar kernel */
__device__ __forceinline__ float exact_dist(const float* zs, const float* emb,
                                            const float* ek2s, int row, int idx) {
    const float* er = emb + (size_t)idx * DDIM;
    float dot = 0.f;
#pragma unroll
    for (int d = 0; d < DDIM; d++)
        dot = fmaf(zs[d * MROWS + row], __ldg(er + d), dot);
    return fmaf(dot, -2.f, ek2s[idx]);
}

/* ================= small kernels ================= */
__global__ void zero_loss_kernel() { g_loss = 0.0; }

__global__ void ek2_kernel(const float* __restrict__ emb) {
    int k = blockIdx.x * blockDim.x + threadIdx.x;
    if (k >= KCODES) return;
    const float4* e4 = (const float4*)(emb + (size_t)k * DDIM);
    float s = 0.f;
#pragma unroll
    for (int i = 0; i < DDIM / 4; i++) {
        float4 v = e4[i];
        s += v.x * v.x + v.y * v.y + v.z * v.z + v.w * v.w;
    }
    g_ek2[k] = s;
}

__global__ void finalize_kernel(float* out, int loss_idx) {
    out[loss_idx] = (float)(g_loss * (1.25 / 8388608.0));
}

/* ================= main kernel ================= */
__global__ void __launch_bounds__(NTHREADS)
vq_kernel(const float* __restrict__ z, const float* __restrict__ emb,
          float* __restrict__ out) {
    extern __shared__ char smem[];
    float* ek2s  = (float*)(smem + SM_EK2);
    int*   idx_s = (int*)(smem + SM_IDX);
    float* wsum  = (float*)(smem + SM_WS);
    float* zs    = (float*)(smem + SM_ZS);     /* [64][128] */
    char*  A4    = smem + SM_A4;
    char*  B4    = smem + SM_B4;

    const int tid  = threadIdx.x;
    const int lane = tid & 31;
    const int w    = tid >> 5;        /* warp id: owns rows w*16 .. w*16+15 */
    const int g    = lane >> 2;       /* group id 0-7 */
    const int t    = lane & 3;        /* thread-in-group 0-3 */

    const int nbase = blockIdx.x * MROWS;
    const int b   = nbase >> 12;
    const int hw0 = nbase & (HW - 1);

    /* ---- ek2 to smem ---- */
#pragma unroll
    for (int it = 0; it < 4; it++)
        ek2s[it * NTHREADS + tid] = g_ek2[it * NTHREADS + tid];

    /* ---- z -> zs [d][row] (coalesced) ---- */
    const float* zb = z + (size_t)b * DDIM * HW + hw0;
#pragma unroll
    for (int it = 0; it < 8; it++) {
        int e4 = it * NTHREADS + tid;            /* 2048 float4 */
        int d = e4 >> 5, r4 = e4 & 31;
        *(float4*)(zs + d * MROWS + r4 * 4) = *(const float4*)(zb + (size_t)d * HW + r4 * 4);
    }
    __syncthreads();

    /* ---- build A4: per (row, kg): float4 j = (hi[8kg+j], hi[8kg+j+4], lo[..j], lo[..j+4]) ---- */
#pragma unroll
    for (int it = 0; it < 4; it++) {
        int p = it * NTHREADS + tid;             /* 1024 (row,kg) pairs */
        int kg = p & 7, row = p >> 3;
        uint32_t hi[8], lo[8];
#pragma unroll
        for (int q = 0; q < 8; q++)
            split_tf32(zs[(kg * 8 + q) * MROWS + row], hi[q], lo[q]);
        char* dst = A4 + (row >> 4) * 8192 + kg * 1024 + (row & 15) * 64;
#pragma unroll
        for (int j = 0; j < 4; j++)
            *(uint4*)(dst + j * 16) = make_uint4(hi[j], hi[j + 4], lo[j], lo[j + 4]);
    }

    /* per-lane top-2 for each of the 2 row-slots */
    float va0 = 3.4e38f, vb0 = 3.4e38f, va1 = 3.4e38f, vb1 = 3.4e38f;
    int   ia0 = 0, ib0 = 0, ia1 = 0, ib1 = 0;

    /* B chunk staging: per thread 2 (kg,n) pairs, gmem-coalesced */
    float4 pf[4], pfn[4];

    auto prefetch = [&](int k0, float4* r) {
#pragma unroll
        for (int it = 0; it < 2; it++) {
            int p = it * NTHREADS + tid;
            int kg = p & 7, n = p >> 3;
            const float4* src = (const float4*)(emb + (size_t)(k0 + n) * DDIM + kg * 8);
            r[it * 2]     = __ldg(src);
            r[it * 2 + 1] = __ldg(src + 1);
        }
    };
    auto sts_b = [&](const float4* r) {
#pragma unroll
        for (int it = 0; it < 2; it++) {
            int p = it * NTHREADS + tid;
            int kg = p & 7, n = p >> 3;
            float v[8] = {r[it*2].x, r[it*2].y, r[it*2].z, r[it*2].w,
                          r[it*2+1].x, r[it*2+1].y, r[it*2+1].z, r[it*2+1].w};
            uint32_t hi[8], lo[8];
#pragma unroll
            for (int q = 0; q < 8; q++) split_tf32(v[q], hi[q], lo[q]);
            char* dst = B4 + kg * 4096 + (n >> 3) * 512 + (n & 7) * 64;
#pragma unroll
            for (int j = 0; j < 4; j++)
                *(uint4*)(dst + j * 16) = make_uint4(hi[j], hi[j + 4], lo[j], lo[j + 4]);
        }
    };

    prefetch(0, pf);
    sts_b(pf);
    __syncthreads();

    const char* aw = A4 + w * 8192;

    for (int c = 0; c < NCHUNKS; c++) {
        const int k0 = c * BK;
        if (c + 1 < NCHUNKS) prefetch(k0 + BK, pfn);

        float C[8][4];
#pragma unroll
        for (int nt = 0; nt < 8; nt++)
#pragma unroll
            for (int q = 0; q < 4; q++) C[nt][q] = 0.f;

#pragma unroll
        for (int kg = 0; kg < 8; kg++) {
            uint4 f1 = *(const uint4*)(aw + kg * 1024 + g * 64 + t * 16);
            uint4 f2 = *(const uint4*)(aw + kg * 1024 + (g + 8) * 64 + t * 16);
            uint32_t ah0 = f1.x, ah1 = f2.x, ah2 = f1.y, ah3 = f2.y;
            uint32_t al0 = f1.z, al1 = f2.z, al2 = f1.w, al3 = f2.w;
            const char* bkg = B4 + kg * 4096 + g * 64 + t * 16;

            /* pass 0: hi*hi */
#pragma unroll
            for (int nt = 0; nt < 8; nt++) {
                uint2 bh = *(const uint2*)(bkg + nt * 512);
                mma_tf32(C[nt][0], C[nt][1], C[nt][2], C[nt][3],
                         ah0, ah1, ah2, ah3, bh.x, bh.y);
            }
            /* pass 1: hi*lo */
#pragma unroll
            for (int nt = 0; nt < 8; nt++) {
                uint2 bl = *(const uint2*)(bkg + nt * 512 + 8);
                mma_tf32(C[nt][0], C[nt][1], C[nt][2], C[nt][3],
                         ah0, ah1, ah2, ah3, bl.x, bl.y);
            }
            /* pass 2: lo*hi */
#pragma unroll
            for (int nt = 0; nt < 8; nt++) {
                uint2 bh = *(const uint2*)(bkg + nt * 512);
                mma_tf32(C[nt][0], C[nt][1], C[nt][2], C[nt][3],
                         al0, al1, al2, al3, bh.x, bh.y);
            }
        }

        /* top-2 update: rows (w*16+g, w*16+8+g), cols k0 + nt*8 + 2t(+1) */
#pragma unroll
        for (int nt = 0; nt < 8; nt++) {
            int c0i = k0 + nt * 8 + 2 * t;
            float2 e2 = *(const float2*)(ek2s + c0i);
            float s0 = fmaf(C[nt][0], -2.f, e2.x);
            float s1 = fmaf(C[nt][1], -2.f, e2.y);
            float s2 = fmaf(C[nt][2], -2.f, e2.x);
            float s3 = fmaf(C[nt][3], -2.f, e2.y);
            if (s0 < va0)      { vb0 = va0; ib0 = ia0; va0 = s0; ia0 = c0i; }
            else if (s0 < vb0) { vb0 = s0; ib0 = c0i; }
            if (s1 < va0)      { vb0 = va0; ib0 = ia0; va0 = s1; ia0 = c0i + 1; }
            else if (s1 < vb0) { vb0 = s1; ib0 = c0i + 1; }
            if (s2 < va1)      { vb1 = va1; ib1 = ia1; va1 = s2; ia1 = c0i; }
            else if (s2 < vb1) { vb1 = s2; ib1 = c0i; }
            if (s3 < va1)      { vb1 = va1; ib1 = ia1; va1 = s3; ia1 = c0i + 1; }
            else if (s3 < vb1) { vb1 = s3; ib1 = c0i + 1; }
        }

        __syncthreads();                   /* done reading B4 chunk c */
        if (c + 1 < NCHUNKS) {
            sts_b(pfn);
            __syncthreads();               /* B4 now chunk c+1 */
        }
    }

    /* ---- cross-lane top-2 merge over t (first-occurrence tie rule on best) ---- */
#pragma unroll
    for (int o = 1; o <= 2; o <<= 1) {
        {
            float pa = __shfl_xor_sync(0xffffffffu, va0, o);
            float pb = __shfl_xor_sync(0xffffffffu, vb0, o);
            int pia = __shfl_xor_sync(0xffffffffu, ia0, o);
            int pib = __shfl_xor_sync(0xffffffffu, ib0, o);
            bool pwin = (pa < va0) || (pa == va0 && pia < ia0);
            if (pwin) {
                bool s2 = (pb < va0) || (pb == va0 && pib < ia0);
                vb0 = s2 ? pb : va0; ib0 = s2 ? pib : ia0;
                va0 = pa; ia0 = pia;
            } else {
                bool s2 = (vb0 < pa) || (vb0 == pa && ib0 < pia);
                vb0 = s2 ? vb0 : pa; ib0 = s2 ? ib0 : pia;
            }
        }
        {
            float pa = __shfl_xor_sync(0xffffffffu, va1, o);
            float pb = __shfl_xor_sync(0xffffffffu, vb1, o);
            int pia = __shfl_xor_sync(0xffffffffu, ia1, o);
            int pib = __shfl_xor_sync(0xffffffffu, ib1, o);
            bool pwin = (pa < va1) || (pa == va1 && pia < ia1);
            if (pwin) {
                bool s2 = (pb < va1) || (pb == va1 && pib < ia1);
                vb1 = s2 ? pb : va1; ib1 = s2 ? pib : ia1;
                va1 = pa; ia1 = pia;
            } else {
                bool s2 = (vb1 < pa) || (vb1 == pa && ib1 < pia);
                vb1 = s2 ? vb1 : pa; ib1 = s2 ? ib1 : pia;
            }
        }
    }

    if (t == 0) {
        int row0 = w * 16 + g, row1 = w * 16 + 8 + g;
        int bi0 = ia0;
        if (vb0 - va0 < EPS) {   /* near-tie: exact fp32 rescue */
            float da = exact_dist(zs, emb, ek2s, row0, ia0);
            float db = exact_dist(zs, emb, ek2s, row0, ib0);
            if (db < da || (db == da && ib0 < ia0)) bi0 = ib0;
        }
        int bi1 = ia1;
        if (vb1 - va1 < EPS) {
            float da = exact_dist(zs, emb, ek2s, row1, ia1);
            float db = exact_dist(zs, emb, ek2s, row1, ib1);
            if (db < da || (db == da && ib1 < ia1)) bi1 = ib1;
        }
        idx_s[row0] = bi0;
        idx_s[row1] = bi1;
    }
    __syncthreads();

    /* ---- epilogue: gather codebook rows, transposed coalesced store, loss ---- */
    float* outb = out + (size_t)b * DDIM * HW + hw0;
    float lsum = 0.f;
#pragma unroll
    for (int it = 0; it < 32; it++) {
        int e = it * NTHREADS + tid;       /* 8192 elements */
        int d = e >> 7, i = e & 127;
        float q = __ldg(emb + (size_t)idx_s[i] * DDIM + d);
        outb[(size_t)d * HW + i] = q;
        float diff = q - zs[d * MROWS + i];
        lsum += diff * diff;
    }
#pragma unroll
    for (int o = 16; o > 0; o >>= 1)
        lsum += __shfl_xor_sync(0xffffffffu, lsum, o);
    if (lane == 0) wsum[w] = lsum;
    __syncthreads();
    if (tid == 0) {
        float tot = 0.f;
#pragma unroll
        for (int j = 0; j < 8; j++) tot += wsum[j];
        atomicAdd(&g_loss, (double)tot);
    }
}

/* ================= launch ================= */
extern "C" void kernel_launch(void* const* d_in, const int* in_sizes, int n_in,
                              void* d_out, int out_size) {
    const float* z   = (const float*)d_in[0];
    const float* emb = (const float*)d_in[1];
    float* out = (float*)d_out;

    static int attr_set = 0;
    if (!attr_set) {
        cudaFuncSetAttribute(vq_kernel, cudaFuncAttributeMaxDynamicSharedMemorySize,
                             SMEM_TOTAL);
        attr_set = 1;
    }

    zero_loss_kernel<<<1, 1>>>();
    ek2_kernel<<<KCODES / 128, 128>>>(emb);
    vq_kernel<<<NTOT / MROWS, NTHREADS, SMEM_TOTAL>>>(z, emb, out);
    finalize_kernel<<<1, 1>>>(out, out_size - 1);
}